// round 14
// baseline (speedup 1.0000x reference)
#include <cuda_runtime.h>

#define HF 64
#define WF 64
#define NPIX 4096
#define M_TOT 48
#define DCH 256

__device__ float g_A[M_TOT * NPIX];
__device__ float g_SA[M_TOT];
__device__ float g_WcT[DCH * DCH];    // WcT[c][o] = sum_k W_dc[o,k]*W_emb[k,c]
__device__ float g_bcomb[DCH];        // bcomb[o] = sum_k W_dc[o,k]*b_emb[k]

// shared-memory union for the merged front kernel
struct GemmSmem {
    float sA[32][268];   // W_dc rows, k-major, padded (bank-conflict-free f4)
    float sB[16][268];   // W_emb cols, k-major
    float bsh[256];
};
struct ScatSmem {
    float Ash[NPIX];
    float partial[16];
};
#define FRONT_SMEM 53248    // >= sizeof(GemmSmem) = 52480

// ---------------------------------------------------------------------------
// K_front: 176 blocks x 512 threads.
//   blocks 0..127  : Wcomb GEMM (32x16 tiles), bcomb, zero d_out
//   blocks 128..175: per-m flow downsample + bilinear weight scatter
// ---------------------------------------------------------------------------
__global__ void __launch_bounds__(512) k_front(
    const float* __restrict__ W_emb, const float* __restrict__ b_emb,
    const float* __restrict__ W_dc,  const float* __restrict__ pmot,
    float* __restrict__ out)
{
    extern __shared__ char smem_raw[];
    int tid = threadIdx.x;

    if (blockIdx.x < 128) {
        // ------------------- GEMM half -------------------
        GemmSmem& S = *reinterpret_cast<GemmSmem*>(smem_raw);
        int bo = blockIdx.x & 7;      // 8 o-tiles of 32
        int bc = blockIdx.x >> 3;     // 16 c-tiles of 16
        int o0 = bo * 32, c0 = bc * 16;

        if (blockIdx.x < M_TOT && tid < 256) out[blockIdx.x * DCH + tid] = 0.f;

#pragma unroll
        for (int e = 0; e < 16; e++) {           // sA: 32x256, coalesced reads
            int idx = e * 512 + tid;
            int o = idx >> 8, k = idx & 255;
            S.sA[o][k] = W_dc[(o0 + o) * DCH + k];
        }
#pragma unroll
        for (int e = 0; e < 8; e++) {            // sB: 16x256 (transpose load)
            int idx = e * 512 + tid;
            int c = idx & 15, k = idx >> 4;
            S.sB[c][k] = W_emb[k * DCH + c0 + c];
        }
        if (bc == 0 && tid < 256) S.bsh[tid] = b_emb[tid];
        __syncthreads();

        int o_l = tid & 31, c_l = tid >> 5;
        const float4* a4 = reinterpret_cast<const float4*>(S.sA[o_l]);
        const float4* b4 = reinterpret_cast<const float4*>(S.sB[c_l]);
        float acc = 0.f;
#pragma unroll 8
        for (int k4 = 0; k4 < 64; k4++) {
            float4 a = a4[k4], b = b4[k4];
            acc += a.x * b.x + a.y * b.y + a.z * b.z + a.w * b.w;
        }
        g_WcT[(c0 + c_l) * DCH + o0 + o_l] = acc;

        if (bc == 0 && tid < 32) {
            const float4* aa = reinterpret_cast<const float4*>(S.sA[tid]);
            const float4* bb = reinterpret_cast<const float4*>(S.bsh);
            float bacc = 0.f;
#pragma unroll 8
            for (int k4 = 0; k4 < 64; k4++) {
                float4 a = aa[k4], b = bb[k4];
                bacc += a.x * b.x + a.y * b.y + a.z * b.z + a.w * b.w;
            }
            g_bcomb[o0 + tid] = bacc;
        }
    } else {
        // ------------------- scatter half -------------------
        ScatSmem& S = *reinterpret_cast<ScatSmem*>(smem_raw);
        int m = blockIdx.x - 128;
        const float4* pm4 = reinterpret_cast<const float4*>(pmot + (size_t)m * 2u * 65536u);

#pragma unroll
        for (int k = 0; k < 8; k++) S.Ash[k * 512 + tid] = 0.f;
        __syncthreads();

        const float inv = 1.0f / 4096.0f;
#pragma unroll
        for (int k = 0; k < 8; k++) {
            int p = k * 512 + tid;        // dest pixel 0..4095
            int i = p >> 6;
            int j = p & 63;

            const float4* ry1 = pm4 + (4 * i + 1) * 64 + j;
            const float4* ry2 = pm4 + (4 * i + 2) * 64 + j;
            float4 a0 = __ldg(ry1);
            float4 a1 = __ldg(ry2);
            float4 b0 = __ldg(ry1 + 16384);   // x-flow channel
            float4 b1 = __ldg(ry2 + 16384);

            float fy = (a0.y + a0.z + a1.y + a1.z) * 0.0625f;  // 2x2 avg * 0.25
            float fx = (b0.y + b0.z + b1.y + b1.z) * 0.0625f;

            float y = (float)i + fy;
            float x = (float)j + fx;
            float y0f = floorf(y), x0f = floorf(x);
            float wy = y - y0f, wx = x - x0f;
            int y0 = (int)y0f, x0 = (int)x0f;
            int y1 = y0 + 1, x1 = x0 + 1;

            float w00 = (1.f - wy) * (1.f - wx) * inv;
            float w01 = (1.f - wy) * wx * inv;
            float w10 = wy * (1.f - wx) * inv;
            float w11 = wy * wx * inv;

            bool vy0 = (y0 >= 0) & (y0 < HF);
            bool vy1 = (y1 >= 0) & (y1 < HF);
            bool vx0 = (x0 >= 0) & (x0 < WF);
            bool vx1 = (x1 >= 0) & (x1 < WF);

            if (vy0 & vx0) atomicAdd(&S.Ash[y0 * WF + x0], w00);
            if (vy0 & vx1) atomicAdd(&S.Ash[y0 * WF + x1], w01);
            if (vy1 & vx0) atomicAdd(&S.Ash[y1 * WF + x0], w10);
            if (vy1 & vx1) atomicAdd(&S.Ash[y1 * WF + x1], w11);
        }
        __syncthreads();

        // copy out + SA = sum(Ash)
        const float4* Ash4 = reinterpret_cast<const float4*>(S.Ash);
        float4* A4 = reinterpret_cast<float4*>(g_A) + m * 1024;
        float s = 0.f;
#pragma unroll
        for (int i = 0; i < 2; i++) {
            float4 v = Ash4[i * 512 + tid];
            A4[i * 512 + tid] = v;
            s += v.x + v.y + v.z + v.w;
        }
#pragma unroll
        for (int off = 16; off; off >>= 1)
            s += __shfl_down_sync(0xffffffffu, s, off);
        int warp = tid >> 5, lane = tid & 31;
        if (lane == 0) S.partial[warp] = s;
        __syncthreads();
        if (warp == 0) {
            float t = (lane < 16) ? S.partial[lane] : 0.f;
#pragma unroll
            for (int off = 8; off; off >>= 1)
                t += __shfl_down_sync(0xffffffffu, t, off);
            if (lane == 0) g_SA[m] = t;
        }
    }
}

// ---------------------------------------------------------------------------
// K_reduce: partial u for 8 channels x 3 m's + Wcomb epilogue.
// grid (16 gf, 32 ctiles), block 256 (8 warps). A in REGISTERS (R8 config).
// NEW: no per-channel shuffle chains. Each thread stores its 3 raw partials
// per channel to shared (stride-3 = conflict-free STS); ONE deferred
// warp-parallel reduction after the loop handles all 24 (ch,m) pairs.
// Hot loop = 4 LDG.128 prefetch + 48 FFMA + 3 STS, no serial dependencies.
// ---------------------------------------------------------------------------
__global__ void __launch_bounds__(256) k_reduce(
    const float* __restrict__ feat, const float* __restrict__ b_dc,
    float* __restrict__ out)
{
    int gf = blockIdx.x;            // 0..15 == b*4+g
    int b = gf >> 2, g = gf & 3;
    int m0 = b * 12 + g * 3;
    int tid = threadIdx.x;
    int warp = tid >> 5, lane = tid & 31;

    const float4* gA4 = reinterpret_cast<const float4*>(g_A);
    float4 a[3][4];
#pragma unroll
    for (int r = 0; r < 3; r++)
#pragma unroll
        for (int k = 0; k < 4; k++)
            a[r][k] = gA4[(m0 + r) * 1024 + k * 256 + tid];

    __shared__ float red[8 * 256 * 3];   // [ch][tid][m] raw partials, 24 KB
    __shared__ float sacc[3][8];

    const float4* F4 = reinterpret_cast<const float4*>(feat)
                     + (size_t)gf * DCH * 1024
                     + (size_t)blockIdx.y * 8 * 1024;

    float4 cur[4], nxt[4];
#pragma unroll
    for (int k = 0; k < 4; k++) cur[k] = F4[k * 256 + tid];

#pragma unroll
    for (int ch = 0; ch < 8; ch++) {
        if (ch < 7) {
#pragma unroll
            for (int k = 0; k < 4; k++)
                nxt[k] = F4[(ch + 1) * 1024 + k * 256 + tid];
        }
        float acc0 = 0.f, acc1 = 0.f, acc2 = 0.f;
#pragma unroll
        for (int k = 0; k < 4; k++) {
            float4 f = cur[k];
            acc0 += a[0][k].x * f.x + a[0][k].y * f.y + a[0][k].z * f.z + a[0][k].w * f.w;
            acc1 += a[1][k].x * f.x + a[1][k].y * f.y + a[1][k].z * f.z + a[1][k].w * f.w;
            acc2 += a[2][k].x * f.x + a[2][k].y * f.y + a[2][k].z * f.z + a[2][k].w * f.w;
        }
        float* rp = &red[ch * 768 + tid * 3];
        rp[0] = acc0;
        rp[1] = acc1;
        rp[2] = acc2;
        if (ch < 7) {
#pragma unroll
            for (int k = 0; k < 4; k++) cur[k] = nxt[k];
        }
    }
    __syncthreads();

    // deferred reduction: warp w handles channel ch=w, all 3 m's.
    // lane sums 8 strided partials per m, then one shuffle tree per m.
#pragma unroll
    for (int r = 0; r < 3; r++) {
        float s = 0.f;
#pragma unroll
        for (int k = 0; k < 8; k++)
            s += red[warp * 768 + (lane + k * 32) * 3 + r];
#pragma unroll
        for (int off = 16; off; off >>= 1)
            s += __shfl_down_sync(0xffffffffu, s, off);
        if (lane == 0) sacc[r][warp] = s;
    }
    __syncthreads();

    // Wcomb epilogue: thread = output channel o
    {
        int o = tid;
        int c0 = blockIdx.y * 8;
        float v0 = 0.f, v1 = 0.f, v2 = 0.f;
#pragma unroll
        for (int ch = 0; ch < 8; ch++) {
            float wv = g_WcT[(c0 + ch) * DCH + o];
            v0 += wv * sacc[0][ch];
            v1 += wv * sacc[1][ch];
            v2 += wv * sacc[2][ch];
        }
        if (blockIdx.y == 0) {
            float bc = g_bcomb[o];
            float bd = b_dc[o];
            v0 += g_SA[m0 + 0] * bc + bd;
            v1 += g_SA[m0 + 1] * bc + bd;
            v2 += g_SA[m0 + 2] * bc + bd;
        }
        atomicAdd(&out[(m0 + 0) * DCH + o], v0);
        atomicAdd(&out[(m0 + 1) * DCH + o], v1);
        atomicAdd(&out[(m0 + 2) * DCH + o], v2);
    }
}

// ---------------------------------------------------------------------------
// inputs (metadata order): imgs, i_features, p_motions, W_emb, b_emb, W_dc, b_dc
// output: float32 [4,4,3,256] = 12288 elements
// ---------------------------------------------------------------------------
extern "C" void kernel_launch(void* const* d_in, const int* in_sizes, int n_in,
                              void* d_out, int out_size) {
    const float* i_features = (const float*)d_in[1];
    const float* p_motions  = (const float*)d_in[2];
    const float* W_emb      = (const float*)d_in[3];
    const float* b_emb      = (const float*)d_in[4];
    const float* W_dc       = (const float*)d_in[5];
    const float* b_dc       = (const float*)d_in[6];
    float* out = (float*)d_out;

    cudaFuncSetAttribute(k_front, cudaFuncAttributeMaxDynamicSharedMemorySize, FRONT_SMEM);
    k_front<<<176, 512, FRONT_SMEM>>>(W_emb, b_emb, W_dc, p_motions, out);
    k_reduce<<<dim3(16, 32), 256>>>(i_features, b_dc, out);
}

// round 15
// speedup vs baseline: 1.0094x; 1.0094x over previous
#include <cuda_runtime.h>

#define HF 64
#define WF 64
#define NPIX 4096
#define M_TOT 48
#define DCH 256

__device__ float g_A[M_TOT * NPIX];
__device__ float g_SA[M_TOT];
__device__ float g_WcT[DCH * DCH];    // WcT[c][o] = sum_k W_dc[o,k]*W_emb[k,c]
__device__ float g_bcomb[DCH];        // bcomb[o] = sum_k W_dc[o,k]*b_emb[k]

// shared-memory union for the merged front kernel
struct GemmSmem {
    float sA[32][268];   // W_dc rows, k-major, padded (bank-conflict-free f4)
    float sB[16][268];   // W_emb cols, k-major
    float bsh[256];
};
struct ScatSmem {
    float Ash[NPIX];
    float partial[16];
};
#define FRONT_SMEM 53248    // >= sizeof(GemmSmem) = 52480

// ---------------------------------------------------------------------------
// K_front: 176 blocks x 512 threads.
//   blocks 0..127  : Wcomb GEMM (32x16 tiles), bcomb, zero d_out
//   blocks 128..175: per-m flow downsample + bilinear weight scatter
// ---------------------------------------------------------------------------
__global__ void __launch_bounds__(512) k_front(
    const float* __restrict__ W_emb, const float* __restrict__ b_emb,
    const float* __restrict__ W_dc,  const float* __restrict__ pmot,
    float* __restrict__ out)
{
    extern __shared__ char smem_raw[];
    int tid = threadIdx.x;

    if (blockIdx.x < 128) {
        // ------------------- GEMM half -------------------
        GemmSmem& S = *reinterpret_cast<GemmSmem*>(smem_raw);
        int bo = blockIdx.x & 7;      // 8 o-tiles of 32
        int bc = blockIdx.x >> 3;     // 16 c-tiles of 16
        int o0 = bo * 32, c0 = bc * 16;

        if (blockIdx.x < M_TOT && tid < 256) out[blockIdx.x * DCH + tid] = 0.f;

#pragma unroll
        for (int e = 0; e < 16; e++) {           // sA: 32x256, coalesced reads
            int idx = e * 512 + tid;
            int o = idx >> 8, k = idx & 255;
            S.sA[o][k] = W_dc[(o0 + o) * DCH + k];
        }
#pragma unroll
        for (int e = 0; e < 8; e++) {            // sB: 16x256 (transpose load)
            int idx = e * 512 + tid;
            int c = idx & 15, k = idx >> 4;
            S.sB[c][k] = W_emb[k * DCH + c0 + c];
        }
        if (bc == 0 && tid < 256) S.bsh[tid] = b_emb[tid];
        __syncthreads();

        int o_l = tid & 31, c_l = tid >> 5;
        const float4* a4 = reinterpret_cast<const float4*>(S.sA[o_l]);
        const float4* b4 = reinterpret_cast<const float4*>(S.sB[c_l]);
        float acc = 0.f;
#pragma unroll 8
        for (int k4 = 0; k4 < 64; k4++) {
            float4 a = a4[k4], b = b4[k4];
            acc += a.x * b.x + a.y * b.y + a.z * b.z + a.w * b.w;
        }
        g_WcT[(c0 + c_l) * DCH + o0 + o_l] = acc;

        if (bc == 0 && tid < 32) {
            const float4* aa = reinterpret_cast<const float4*>(S.sA[tid]);
            const float4* bb = reinterpret_cast<const float4*>(S.bsh);
            float bacc = 0.f;
#pragma unroll 8
            for (int k4 = 0; k4 < 64; k4++) {
                float4 a = aa[k4], b = bb[k4];
                bacc += a.x * b.x + a.y * b.y + a.z * b.z + a.w * b.w;
            }
            g_bcomb[o0 + tid] = bacc;
        }
    } else {
        // ------------------- scatter half -------------------
        ScatSmem& S = *reinterpret_cast<ScatSmem*>(smem_raw);
        int m = blockIdx.x - 128;
        const float4* pm4 = reinterpret_cast<const float4*>(pmot + (size_t)m * 2u * 65536u);

#pragma unroll
        for (int k = 0; k < 8; k++) S.Ash[k * 512 + tid] = 0.f;
        __syncthreads();

        const float inv = 1.0f / 4096.0f;
#pragma unroll
        for (int k = 0; k < 8; k++) {
            int p = k * 512 + tid;        // dest pixel 0..4095
            int i = p >> 6;
            int j = p & 63;

            const float4* ry1 = pm4 + (4 * i + 1) * 64 + j;
            const float4* ry2 = pm4 + (4 * i + 2) * 64 + j;
            float4 a0 = __ldg(ry1);
            float4 a1 = __ldg(ry2);
            float4 b0 = __ldg(ry1 + 16384);   // x-flow channel
            float4 b1 = __ldg(ry2 + 16384);

            float fy = (a0.y + a0.z + a1.y + a1.z) * 0.0625f;  // 2x2 avg * 0.25
            float fx = (b0.y + b0.z + b1.y + b1.z) * 0.0625f;

            float y = (float)i + fy;
            float x = (float)j + fx;
            float y0f = floorf(y), x0f = floorf(x);
            float wy = y - y0f, wx = x - x0f;
            int y0 = (int)y0f, x0 = (int)x0f;
            int y1 = y0 + 1, x1 = x0 + 1;

            float w00 = (1.f - wy) * (1.f - wx) * inv;
            float w01 = (1.f - wy) * wx * inv;
            float w10 = wy * (1.f - wx) * inv;
            float w11 = wy * wx * inv;

            bool vy0 = (y0 >= 0) & (y0 < HF);
            bool vy1 = (y1 >= 0) & (y1 < HF);
            bool vx0 = (x0 >= 0) & (x0 < WF);
            bool vx1 = (x1 >= 0) & (x1 < WF);

            if (vy0 & vx0) atomicAdd(&S.Ash[y0 * WF + x0], w00);
            if (vy0 & vx1) atomicAdd(&S.Ash[y0 * WF + x1], w01);
            if (vy1 & vx0) atomicAdd(&S.Ash[y1 * WF + x0], w10);
            if (vy1 & vx1) atomicAdd(&S.Ash[y1 * WF + x1], w11);
        }
        __syncthreads();

        // copy out + SA = sum(Ash)
        const float4* Ash4 = reinterpret_cast<const float4*>(S.Ash);
        float4* A4 = reinterpret_cast<float4*>(g_A) + m * 1024;
        float s = 0.f;
#pragma unroll
        for (int i = 0; i < 2; i++) {
            float4 v = Ash4[i * 512 + tid];
            A4[i * 512 + tid] = v;
            s += v.x + v.y + v.z + v.w;
        }
#pragma unroll
        for (int off = 16; off; off >>= 1)
            s += __shfl_down_sync(0xffffffffu, s, off);
        int warp = tid >> 5, lane = tid & 31;
        if (lane == 0) S.partial[warp] = s;
        __syncthreads();
        if (warp == 0) {
            float t = (lane < 16) ? S.partial[lane] : 0.f;
#pragma unroll
            for (int off = 8; off; off >>= 1)
                t += __shfl_down_sync(0xffffffffu, t, off);
            if (lane == 0) g_SA[m] = t;
        }
    }
}

// ---------------------------------------------------------------------------
// K_reduce: partial u for 8 channels x 3 m's + Wcomb epilogue.
// grid (16 gf, 32 ctiles), block 256, pinned 3 blocks/SM.
// LOOP ORDER SWAPPED vs R14: k (pixel chunk) outer, channel inner. Per
// k-iter each thread issues 8 INDEPENDENT feature float4 loads (one per
// channel) -> 24 warps x 8 f4 = 24 KB in flight per SM, ~2x R14's depth.
// Accumulators persist across k; hot loop has no STS/SHFL. One deferred
// warp-parallel reduction + Wcomb epilogue at the end (R14 scheme).
// ---------------------------------------------------------------------------
__global__ void __launch_bounds__(256, 3) k_reduce(
    const float* __restrict__ feat, const float* __restrict__ b_dc,
    float* __restrict__ out)
{
    int gf = blockIdx.x;            // 0..15 == b*4+g
    int b = gf >> 2, g = gf & 3;
    int m0 = b * 12 + g * 3;
    int tid = threadIdx.x;
    int warp = tid >> 5, lane = tid & 31;

    const float4* gA4 = reinterpret_cast<const float4*>(g_A) + m0 * 1024;
    const float4* F4 = reinterpret_cast<const float4*>(feat)
                     + (size_t)gf * DCH * 1024
                     + (size_t)blockIdx.y * 8 * 1024;

    float acc[8][3];
#pragma unroll
    for (int ch = 0; ch < 8; ch++)
#pragma unroll
        for (int r = 0; r < 3; r++) acc[ch][r] = 0.f;

#pragma unroll
    for (int k = 0; k < 4; k++) {
        // A weights for this pixel chunk (L2/L1-resident, reread cheap)
        float4 a0 = gA4[0 * 1024 + k * 256 + tid];
        float4 a1 = gA4[1 * 1024 + k * 256 + tid];
        float4 a2 = gA4[2 * 1024 + k * 256 + tid];
        // 8 independent feature loads, all in flight together
        float4 f[8];
#pragma unroll
        for (int ch = 0; ch < 8; ch++)
            f[ch] = F4[ch * 1024 + k * 256 + tid];
#pragma unroll
        for (int ch = 0; ch < 8; ch++) {
            acc[ch][0] += a0.x * f[ch].x + a0.y * f[ch].y + a0.z * f[ch].z + a0.w * f[ch].w;
            acc[ch][1] += a1.x * f[ch].x + a1.y * f[ch].y + a1.z * f[ch].z + a1.w * f[ch].w;
            acc[ch][2] += a2.x * f[ch].x + a2.y * f[ch].y + a2.z * f[ch].z + a2.w * f[ch].w;
        }
    }

    __shared__ float red[8 * 256 * 3];   // [ch][tid][m] raw partials, 24 KB
    __shared__ float sacc[3][8];
#pragma unroll
    for (int ch = 0; ch < 8; ch++) {
        float* rp = &red[ch * 768 + tid * 3];
        rp[0] = acc[ch][0];
        rp[1] = acc[ch][1];
        rp[2] = acc[ch][2];
    }
    __syncthreads();

    // deferred reduction: warp w handles channel ch=w, all 3 m's
#pragma unroll
    for (int r = 0; r < 3; r++) {
        float s = 0.f;
#pragma unroll
        for (int k = 0; k < 8; k++)
            s += red[warp * 768 + (lane + k * 32) * 3 + r];
#pragma unroll
        for (int off = 16; off; off >>= 1)
            s += __shfl_down_sync(0xffffffffu, s, off);
        if (lane == 0) sacc[r][warp] = s;
    }
    __syncthreads();

    // Wcomb epilogue: thread = output channel o
    {
        int o = tid;
        int c0 = blockIdx.y * 8;
        float v0 = 0.f, v1 = 0.f, v2 = 0.f;
#pragma unroll
        for (int ch = 0; ch < 8; ch++) {
            float wv = g_WcT[(c0 + ch) * DCH + o];
            v0 += wv * sacc[0][ch];
            v1 += wv * sacc[1][ch];
            v2 += wv * sacc[2][ch];
        }
        if (blockIdx.y == 0) {
            float bc = g_bcomb[o];
            float bd = b_dc[o];
            v0 += g_SA[m0 + 0] * bc + bd;
            v1 += g_SA[m0 + 1] * bc + bd;
            v2 += g_SA[m0 + 2] * bc + bd;
        }
        atomicAdd(&out[(m0 + 0) * DCH + o], v0);
        atomicAdd(&out[(m0 + 1) * DCH + o], v1);
        atomicAdd(&out[(m0 + 2) * DCH + o], v2);
    }
}

// ---------------------------------------------------------------------------
// inputs (metadata order): imgs, i_features, p_motions, W_emb, b_emb, W_dc, b_dc
// output: float32 [4,4,3,256] = 12288 elements
// ---------------------------------------------------------------------------
extern "C" void kernel_launch(void* const* d_in, const int* in_sizes, int n_in,
                              void* d_out, int out_size) {
    const float* i_features = (const float*)d_in[1];
    const float* p_motions  = (const float*)d_in[2];
    const float* W_emb      = (const float*)d_in[3];
    const float* b_emb      = (const float*)d_in[4];
    const float* W_dc       = (const float*)d_in[5];
    const float* b_dc       = (const float*)d_in[6];
    float* out = (float*)d_out;

    cudaFuncSetAttribute(k_front, cudaFuncAttributeMaxDynamicSharedMemorySize, FRONT_SMEM);
    k_front<<<176, 512, FRONT_SMEM>>>(W_emb, b_emb, W_dc, p_motions, out);
    k_reduce<<<dim3(16, 32), 256>>>(i_features, b_dc, out);
}

// round 16
// speedup vs baseline: 1.0647x; 1.0547x over previous
#include <cuda_runtime.h>

#define HF 64
#define WF 64
#define NPIX 4096
#define M_TOT 48
#define DCH 256

__device__ float g_A[M_TOT * NPIX];
__device__ float g_SA[M_TOT];
__device__ float g_WcT[DCH * DCH];    // WcT[c][o] = sum_k W_dc[o,k]*W_emb[k,c]
__device__ float g_bcomb[DCH];        // bcomb[o] = sum_k W_dc[o,k]*b_emb[k]

// shared-memory union for the merged front kernel
struct GemmSmem {
    float sA[32][268];   // W_dc rows, k-major, padded (bank-conflict-free f4)
    float sB[16][268];   // W_emb cols, k-major
    float bsh[256];
};
struct ScatSmem {
    float Ash[NPIX];
    float partial[16];
};
#define FRONT_SMEM 53248    // >= sizeof(GemmSmem) = 52480

// ---------------------------------------------------------------------------
// K_front: 176 blocks x 512 threads.
//   blocks 0..127  : Wcomb GEMM (32x16 tiles), bcomb, zero d_out
//   blocks 128..175: per-m flow downsample + bilinear weight scatter
// ---------------------------------------------------------------------------
__global__ void __launch_bounds__(512) k_front(
    const float* __restrict__ W_emb, const float* __restrict__ b_emb,
    const float* __restrict__ W_dc,  const float* __restrict__ pmot,
    float* __restrict__ out)
{
    extern __shared__ char smem_raw[];
    int tid = threadIdx.x;

    if (blockIdx.x < 128) {
        // ------------------- GEMM half -------------------
        GemmSmem& S = *reinterpret_cast<GemmSmem*>(smem_raw);
        int bo = blockIdx.x & 7;      // 8 o-tiles of 32
        int bc = blockIdx.x >> 3;     // 16 c-tiles of 16
        int o0 = bo * 32, c0 = bc * 16;

        if (blockIdx.x < M_TOT && tid < 256) out[blockIdx.x * DCH + tid] = 0.f;

#pragma unroll
        for (int e = 0; e < 16; e++) {           // sA: 32x256, coalesced reads
            int idx = e * 512 + tid;
            int o = idx >> 8, k = idx & 255;
            S.sA[o][k] = W_dc[(o0 + o) * DCH + k];
        }
#pragma unroll
        for (int e = 0; e < 8; e++) {            // sB: 16x256 (transpose load)
            int idx = e * 512 + tid;
            int c = idx & 15, k = idx >> 4;
            S.sB[c][k] = W_emb[k * DCH + c0 + c];
        }
        if (bc == 0 && tid < 256) S.bsh[tid] = b_emb[tid];
        __syncthreads();

        int o_l = tid & 31, c_l = tid >> 5;
        const float4* a4 = reinterpret_cast<const float4*>(S.sA[o_l]);
        const float4* b4 = reinterpret_cast<const float4*>(S.sB[c_l]);
        float acc = 0.f;
#pragma unroll 8
        for (int k4 = 0; k4 < 64; k4++) {
            float4 a = a4[k4], b = b4[k4];
            acc += a.x * b.x + a.y * b.y + a.z * b.z + a.w * b.w;
        }
        g_WcT[(c0 + c_l) * DCH + o0 + o_l] = acc;

        if (bc == 0 && tid < 32) {
            const float4* aa = reinterpret_cast<const float4*>(S.sA[tid]);
            const float4* bb = reinterpret_cast<const float4*>(S.bsh);
            float bacc = 0.f;
#pragma unroll 8
            for (int k4 = 0; k4 < 64; k4++) {
                float4 a = aa[k4], b = bb[k4];
                bacc += a.x * b.x + a.y * b.y + a.z * b.z + a.w * b.w;
            }
            g_bcomb[o0 + tid] = bacc;
        }
    } else {
        // ------------------- scatter half -------------------
        ScatSmem& S = *reinterpret_cast<ScatSmem*>(smem_raw);
        int m = blockIdx.x - 128;
        const float4* pm4 = reinterpret_cast<const float4*>(pmot + (size_t)m * 2u * 65536u);

#pragma unroll
        for (int k = 0; k < 8; k++) S.Ash[k * 512 + tid] = 0.f;
        __syncthreads();

        const float inv = 1.0f / 4096.0f;
#pragma unroll
        for (int k = 0; k < 8; k++) {
            int p = k * 512 + tid;        // dest pixel 0..4095
            int i = p >> 6;
            int j = p & 63;

            const float4* ry1 = pm4 + (4 * i + 1) * 64 + j;
            const float4* ry2 = pm4 + (4 * i + 2) * 64 + j;
            float4 a0 = __ldg(ry1);
            float4 a1 = __ldg(ry2);
            float4 b0 = __ldg(ry1 + 16384);   // x-flow channel
            float4 b1 = __ldg(ry2 + 16384);

            float fy = (a0.y + a0.z + a1.y + a1.z) * 0.0625f;  // 2x2 avg * 0.25
            float fx = (b0.y + b0.z + b1.y + b1.z) * 0.0625f;

            float y = (float)i + fy;
            float x = (float)j + fx;
            float y0f = floorf(y), x0f = floorf(x);
            float wy = y - y0f, wx = x - x0f;
            int y0 = (int)y0f, x0 = (int)x0f;
            int y1 = y0 + 1, x1 = x0 + 1;

            float w00 = (1.f - wy) * (1.f - wx) * inv;
            float w01 = (1.f - wy) * wx * inv;
            float w10 = wy * (1.f - wx) * inv;
            float w11 = wy * wx * inv;

            bool vy0 = (y0 >= 0) & (y0 < HF);
            bool vy1 = (y1 >= 0) & (y1 < HF);
            bool vx0 = (x0 >= 0) & (x0 < WF);
            bool vx1 = (x1 >= 0) & (x1 < WF);

            if (vy0 & vx0) atomicAdd(&S.Ash[y0 * WF + x0], w00);
            if (vy0 & vx1) atomicAdd(&S.Ash[y0 * WF + x1], w01);
            if (vy1 & vx0) atomicAdd(&S.Ash[y1 * WF + x0], w10);
            if (vy1 & vx1) atomicAdd(&S.Ash[y1 * WF + x1], w11);
        }
        __syncthreads();

        // copy out + SA = sum(Ash)
        const float4* Ash4 = reinterpret_cast<const float4*>(S.Ash);
        float4* A4 = reinterpret_cast<float4*>(g_A) + m * 1024;
        float s = 0.f;
#pragma unroll
        for (int i = 0; i < 2; i++) {
            float4 v = Ash4[i * 512 + tid];
            A4[i * 512 + tid] = v;
            s += v.x + v.y + v.z + v.w;
        }
#pragma unroll
        for (int off = 16; off; off >>= 1)
            s += __shfl_down_sync(0xffffffffu, s, off);
        int warp = tid >> 5, lane = tid & 31;
        if (lane == 0) S.partial[warp] = s;
        __syncthreads();
        if (warp == 0) {
            float t = (lane < 16) ? S.partial[lane] : 0.f;
#pragma unroll
            for (int off = 8; off; off >>= 1)
                t += __shfl_down_sync(0xffffffffu, t, off);
            if (lane == 0) g_SA[m] = t;
        }
    }
}

// ---------------------------------------------------------------------------
// K_reduce: partial u for 4 channels x 3 m's + Wcomb epilogue.
// grid (16 gf, 64 ctiles of 4 channels) = 1024 blocks, 256 threads,
// pinned 4 blocks/SM (~55 regs). Halved unit size kills the 2-wave tail:
// 1024 units / 592 slots -> makespan ~2 x T/2 = T (vs R15's 2T with 512/444).
// k outer, channels inner: 4 independent feature f4 loads + 3 A f4 per iter,
// accumulators persist, no STS/SHFL in the hot loop.
// ---------------------------------------------------------------------------
__global__ void __launch_bounds__(256, 4) k_reduce(
    const float* __restrict__ feat, const float* __restrict__ b_dc,
    float* __restrict__ out)
{
    int gf = blockIdx.x;            // 0..15 == b*4+g
    int b = gf >> 2, g = gf & 3;
    int m0 = b * 12 + g * 3;
    int tid = threadIdx.x;
    int warp = tid >> 5, lane = tid & 31;

    const float4* gA4 = reinterpret_cast<const float4*>(g_A) + m0 * 1024;
    const float4* F4 = reinterpret_cast<const float4*>(feat)
                     + (size_t)gf * DCH * 1024
                     + (size_t)blockIdx.y * 4 * 1024;

    float acc[4][3];
#pragma unroll
    for (int ch = 0; ch < 4; ch++)
#pragma unroll
        for (int r = 0; r < 3; r++) acc[ch][r] = 0.f;

#pragma unroll
    for (int k = 0; k < 4; k++) {
        float4 a0 = gA4[0 * 1024 + k * 256 + tid];
        float4 a1 = gA4[1 * 1024 + k * 256 + tid];
        float4 a2 = gA4[2 * 1024 + k * 256 + tid];
        float4 f[4];
#pragma unroll
        for (int ch = 0; ch < 4; ch++)
            f[ch] = F4[ch * 1024 + k * 256 + tid];
#pragma unroll
        for (int ch = 0; ch < 4; ch++) {
            acc[ch][0] += a0.x * f[ch].x + a0.y * f[ch].y + a0.z * f[ch].z + a0.w * f[ch].w;
            acc[ch][1] += a1.x * f[ch].x + a1.y * f[ch].y + a1.z * f[ch].z + a1.w * f[ch].w;
            acc[ch][2] += a2.x * f[ch].x + a2.y * f[ch].y + a2.z * f[ch].z + a2.w * f[ch].w;
        }
    }

    __shared__ float red[4 * 256 * 3];   // [ch][tid][m] raw partials, 12 KB
    __shared__ float sacc[3][4];
#pragma unroll
    for (int ch = 0; ch < 4; ch++) {
        float* rp = &red[ch * 768 + tid * 3];
        rp[0] = acc[ch][0];
        rp[1] = acc[ch][1];
        rp[2] = acc[ch][2];
    }
    __syncthreads();

    // deferred reduction: warps 0..3 handle channel ch=warp, all 3 m's
    if (warp < 4) {
#pragma unroll
        for (int r = 0; r < 3; r++) {
            float s = 0.f;
#pragma unroll
            for (int k = 0; k < 8; k++)
                s += red[warp * 768 + (lane + k * 32) * 3 + r];
#pragma unroll
            for (int off = 16; off; off >>= 1)
                s += __shfl_down_sync(0xffffffffu, s, off);
            if (lane == 0) sacc[r][warp] = s;
        }
    }
    __syncthreads();

    // Wcomb epilogue: thread = output channel o
    {
        int o = tid;
        int c0 = blockIdx.y * 4;
        float v0 = 0.f, v1 = 0.f, v2 = 0.f;
#pragma unroll
        for (int ch = 0; ch < 4; ch++) {
            float wv = g_WcT[(c0 + ch) * DCH + o];
            v0 += wv * sacc[0][ch];
            v1 += wv * sacc[1][ch];
            v2 += wv * sacc[2][ch];
        }
        if (blockIdx.y == 0) {
            float bc = g_bcomb[o];
            float bd = b_dc[o];
            v0 += g_SA[m0 + 0] * bc + bd;
            v1 += g_SA[m0 + 1] * bc + bd;
            v2 += g_SA[m0 + 2] * bc + bd;
        }
        atomicAdd(&out[(m0 + 0) * DCH + o], v0);
        atomicAdd(&out[(m0 + 1) * DCH + o], v1);
        atomicAdd(&out[(m0 + 2) * DCH + o], v2);
    }
}

// ---------------------------------------------------------------------------
// inputs (metadata order): imgs, i_features, p_motions, W_emb, b_emb, W_dc, b_dc
// output: float32 [4,4,3,256] = 12288 elements
// ---------------------------------------------------------------------------
extern "C" void kernel_launch(void* const* d_in, const int* in_sizes, int n_in,
                              void* d_out, int out_size) {
    const float* i_features = (const float*)d_in[1];
    const float* p_motions  = (const float*)d_in[2];
    const float* W_emb      = (const float*)d_in[3];
    const float* b_emb      = (const float*)d_in[4];
    const float* W_dc       = (const float*)d_in[5];
    const float* b_dc       = (const float*)d_in[6];
    float* out = (float*)d_out;

    cudaFuncSetAttribute(k_front, cudaFuncAttributeMaxDynamicSharedMemorySize, FRONT_SMEM);
    k_front<<<176, 512, FRONT_SMEM>>>(W_emb, b_emb, W_dc, p_motions, out);
    k_reduce<<<dim3(16, 64), 256>>>(i_features, b_dc, out);
}